// round 6
// baseline (speedup 1.0000x reference)
#include <cuda_runtime.h>

// Shapes (fixed by the problem)
#define BB   4
#define CC   128
#define HH   64
#define WW   64
#define HWSZ 4096              // 64*64
#define CHW  (CC*HWSZ)         // 128*4096

// Scratch (device globals -- no allocation allowed)
__device__ float g_buf[BB*CHW];   // silu(GN(x)) / silu(GN(h))
__device__ float g_h[BB*CHW];     // h
__device__ float g_c[BB*CHW];     // c = 1x1 conv of cond
__device__ float g_temb[BB*CC];   // time embedding

__device__ __forceinline__ float silu_f(float v) { return v / (1.0f + __expf(-v)); }

// ---------------------------------------------------------------------------
// temb[b,o] = sum_k silu(t[b,k]) * mlp_w[o,k] + mlp_b[o]     (tiny)
// grid 1, block 512 (tid = b*128 + o)
// ---------------------------------------------------------------------------
__global__ void temb_kernel(const float* __restrict__ t,
                            const float* __restrict__ w,
                            const float* __restrict__ bias) {
    __shared__ float st[BB*512];
    int tid = threadIdx.x;
    for (int e = tid; e < BB*512; e += 512) st[e] = silu_f(t[e]);
    __syncthreads();
    int b = tid >> 7, o = tid & 127;
    const float* wr = w + o*512;
    const float* tr = st + b*512;
    float s = 0.f;
#pragma unroll 8
    for (int k = 0; k < 512; ++k) s += tr[k]*wr[k];
    g_temb[tid] = s + bias[o];
}

// ---------------------------------------------------------------------------
// GroupNorm(32 groups) + SiLU.  One block per (b,g): 4 channels * 4096 = 16384
// contiguous floats.  grid 128, block 256.
// ---------------------------------------------------------------------------
__global__ void gn_silu_kernel(const float* __restrict__ in,
                               const float* __restrict__ scale,
                               const float* __restrict__ bias,
                               float* __restrict__ out) {
    __shared__ float red[32];
    int tid = threadIdx.x;
    const float4* p = (const float4*)(in  + (size_t)blockIdx.x * 16384);
    float4*       q = (float4*)      (out + (size_t)blockIdx.x * 16384);
    float s = 0.f, sq = 0.f;
#pragma unroll 4
    for (int k = 0; k < 16; ++k) {
        float4 a = p[tid + k*256];
        s  += a.x + a.y + a.z + a.w;
        sq += a.x*a.x + a.y*a.y + a.z*a.z + a.w*a.w;
    }
#pragma unroll
    for (int o = 16; o > 0; o >>= 1) {
        s  += __shfl_xor_sync(0xffffffffu, s,  o);
        sq += __shfl_xor_sync(0xffffffffu, sq, o);
    }
    int wp = tid >> 5, lane = tid & 31;
    if (lane == 0) { red[wp] = s; red[wp + 8] = sq; }
    __syncthreads();
    if (tid == 0) {
        float ts = 0.f, tq2 = 0.f;
        for (int i = 0; i < 8; ++i) { ts += red[i]; tq2 += red[i + 8]; }
        float mean = ts * (1.0f/16384.0f);
        float var  = tq2 * (1.0f/16384.0f) - mean*mean;
        red[16] = mean;
        red[17] = rsqrtf(var + 1e-5f);
    }
    __syncthreads();
    float mean = red[16], rstd = red[17];
    int g = blockIdx.x & 31;
#pragma unroll 4
    for (int k = 0; k < 16; ++k) {
        int idx = tid + k*256;
        int c = g*4 + (idx >> 10);          // 1024 float4 per channel
        float sc = scale[c] * rstd;
        float bi = bias[c] - mean * sc;
        float4 a = p[idx];
        float4 r;
        r.x = silu_f(fmaf(a.x, sc, bi));
        r.y = silu_f(fmaf(a.y, sc, bi));
        r.z = silu_f(fmaf(a.z, sc, bi));
        r.w = silu_f(fmaf(a.w, sc, bi));
        q[idx] = r;
    }
}

// ---------------------------------------------------------------------------
// 3x3 conv, pad 1.  CTA: 16x16 pixel tile x 32 out channels, b fixed.
// grid (16 tiles, 4 o-blocks, 4 batch), block 256.
// Thread: 2x2 pixels x 8 out channels (32 accumulators).
// Epilogue: + bias, optional +temb[b,o], optional +resid (residual x).
// ---------------------------------------------------------------------------
__global__ void __launch_bounds__(256) conv3x3_kernel(
    const float* __restrict__ in, const float* __restrict__ wgt,
    const float* __restrict__ bias, const float* __restrict__ temb,
    const float* __restrict__ resid, float* __restrict__ out) {
    __shared__ float sIn[8*18*18];            // 2592 floats
    __shared__ float sW[72*33];               // [ci*9+rs][o], stride 33 (pad)
    int tid = threadIdx.x;
    int b  = blockIdx.z;
    int ob = blockIdx.y * 32;
    int tx0 = (blockIdx.x & 3) * 16;
    int ty0 = (blockIdx.x >> 2) * 16;
    int og = tid & 3;                         // out-channel group (8 each)
    int pb = tid >> 2;                        // 0..63 pixel blocks
    int lx = (pb & 7) * 2;
    int ly = (pb >> 3) * 2;
    float acc[8][4];
#pragma unroll
    for (int j = 0; j < 8; ++j)
#pragma unroll
        for (int i = 0; i < 4; ++i) acc[j][i] = 0.f;

    const float* inb = in + (size_t)b * CHW;
    const float* wb  = wgt + (size_t)ob * 1152;       // 128*9

    for (int cc = 0; cc < 16; ++cc) {
        __syncthreads();
        int ci0 = cc * 8;
        for (int e = tid; e < 2592; e += 256) {
            int ci = e / 324; int rem = e - ci*324;
            int yy = rem / 18; int xx = rem - yy*18;
            int gy = ty0 - 1 + yy, gx = tx0 - 1 + xx;
            float v = 0.f;
            if ((unsigned)gy < 64u && (unsigned)gx < 64u)
                v = inb[(ci0 + ci)*HWSZ + gy*64 + gx];
            sIn[e] = v;
        }
        for (int e = tid; e < 2304; e += 256) {
            int o = e / 72; int irs = e - o*72;       // irs = ci*9 + rs
            sW[irs*33 + o] = wb[o*1152 + ci0*9 + irs];
        }
        __syncthreads();
#pragma unroll 2
        for (int ci = 0; ci < 8; ++ci) {
            const float* sbase = sIn + ci*324;
#pragma unroll
            for (int rs = 0; rs < 9; ++rs) {
                int r = rs / 3, sx = rs - (rs/3)*3;
                const float* rowp = sbase + (ly + r)*18 + lx + sx;
                float x00 = rowp[0],  x01 = rowp[1];
                float x10 = rowp[18], x11 = rowp[19];
                const float* wp = sW + (ci*9 + rs)*33 + og*8;
#pragma unroll
                for (int j = 0; j < 8; ++j) {
                    float wv = wp[j];
                    acc[j][0] = fmaf(wv, x00, acc[j][0]);
                    acc[j][1] = fmaf(wv, x01, acc[j][1]);
                    acc[j][2] = fmaf(wv, x10, acc[j][2]);
                    acc[j][3] = fmaf(wv, x11, acc[j][3]);
                }
            }
        }
    }
    int px = tx0 + lx, py = ty0 + ly;
#pragma unroll
    for (int j = 0; j < 8; ++j) {
        int o = ob + og*8 + j;
        float add = bias[o];
        if (temb) add += temb[b*CC + o];
        int base = (b*CC + o) * HWSZ;
#pragma unroll
        for (int dy = 0; dy < 2; ++dy)
#pragma unroll
            for (int dx = 0; dx < 2; ++dx) {
                int idx = base + (py + dy)*64 + (px + dx);
                float v = acc[j][dy*2 + dx] + add;
                if (resid) v += resid[idx];
                out[idx] = v;
            }
    }
}

// ---------------------------------------------------------------------------
// 1x1 conv: c[b,o,p] = sum_i cond_w[o,i]*cond[b,i,p] + cond_b[o]  -> g_c
// grid (32 o-groups of 4, 4 batch), block 256; thread: 4 outs x 16 px.
// ---------------------------------------------------------------------------
__global__ void __launch_bounds__(256) cond1x1_kernel(
    const float* __restrict__ cond, const float* __restrict__ w,
    const float* __restrict__ bias) {
    __shared__ float sw[512];
    int tid = threadIdx.x;
    int o0 = blockIdx.x * 4;
    int b  = blockIdx.y;
    for (int e = tid; e < 512; e += 256)
        sw[e] = w[(o0 + (e >> 7))*128 + (e & 127)];
    __syncthreads();
    float acc[4][16];
#pragma unroll
    for (int j = 0; j < 4; ++j)
#pragma unroll
        for (int k = 0; k < 16; ++k) acc[j][k] = 0.f;
    const float4* cp = (const float4*)(cond + (size_t)b * CHW);
    for (int i = 0; i < 128; ++i) {
        float w0 = sw[i], w1 = sw[128 + i], w2 = sw[256 + i], w3 = sw[384 + i];
#pragma unroll
        for (int k = 0; k < 4; ++k) {
            float4 xv = cp[i*1024 + k*256 + tid];
            acc[0][k*4+0] = fmaf(w0, xv.x, acc[0][k*4+0]);
            acc[0][k*4+1] = fmaf(w0, xv.y, acc[0][k*4+1]);
            acc[0][k*4+2] = fmaf(w0, xv.z, acc[0][k*4+2]);
            acc[0][k*4+3] = fmaf(w0, xv.w, acc[0][k*4+3]);
            acc[1][k*4+0] = fmaf(w1, xv.x, acc[1][k*4+0]);
            acc[1][k*4+1] = fmaf(w1, xv.y, acc[1][k*4+1]);
            acc[1][k*4+2] = fmaf(w1, xv.z, acc[1][k*4+2]);
            acc[1][k*4+3] = fmaf(w1, xv.w, acc[1][k*4+3]);
            acc[2][k*4+0] = fmaf(w2, xv.x, acc[2][k*4+0]);
            acc[2][k*4+1] = fmaf(w2, xv.y, acc[2][k*4+1]);
            acc[2][k*4+2] = fmaf(w2, xv.z, acc[2][k*4+2]);
            acc[2][k*4+3] = fmaf(w2, xv.w, acc[2][k*4+3]);
            acc[3][k*4+0] = fmaf(w3, xv.x, acc[3][k*4+0]);
            acc[3][k*4+1] = fmaf(w3, xv.y, acc[3][k*4+1]);
            acc[3][k*4+2] = fmaf(w3, xv.z, acc[3][k*4+2]);
            acc[3][k*4+3] = fmaf(w3, xv.w, acc[3][k*4+3]);
        }
    }
#pragma unroll
    for (int j = 0; j < 4; ++j) {
        float bj = bias[o0 + j];
        float4* op = (float4*)(g_c + ((size_t)b*CC + o0 + j) * HWSZ);
#pragma unroll
        for (int k = 0; k < 4; ++k) {
            float4 v;
            v.x = acc[j][k*4+0] + bj; v.y = acc[j][k*4+1] + bj;
            v.z = acc[j][k*4+2] + bj; v.w = acc[j][k*4+3] + bj;
            op[k*256 + tid] = v;
        }
    }
}

// ---------------------------------------------------------------------------
// Streaming spatial cross-attention + contrast-embed add.
// One CTA per (b, w): A[q][hh] = sum_c H[c][hh]*C[c][q] (64x64 per chunk),
// row-softmax (softmax over hh axis == dim 1 of score), Out += C * P^T.
// h[b,c,hh,w] += Out[c][hh] + contrast_embed[aim[b]][c]
// grid (64 w, 4 b), block 256, dynamic smem 80KB.
// ---------------------------------------------------------------------------
__global__ void __launch_bounds__(256) attn_kernel(
    float* __restrict__ h, const float* __restrict__ cmat,
    const float* __restrict__ ce_tab, const int* __restrict__ aim) {
    extern __shared__ float smem[];
    float* sH = smem;             // [128][64]
    float* sC = smem + 8192;      // [128][64]
    float* sA = smem + 16384;     // [64 q][64 hh]
    int tid = threadIdx.x;
    int w = blockIdx.x;
    int b = blockIdx.y;
    float*       hb = h    + (size_t)b * CHW;
    const float* cb = cmat + (size_t)b * CHW;

    for (int e = tid; e < 8192; e += 256) {
        int c = e >> 6, hh = e & 63;
        sH[e] = hb[c*HWSZ + hh*64 + w];
    }
    float oa[8][4];
#pragma unroll
    for (int j = 0; j < 8; ++j)
#pragma unroll
        for (int i = 0; i < 4; ++i) oa[j][i] = 0.f;

    const int th = tid & 15;          // -> hh base th*4
    const int tq = tid >> 4;          // -> q base tq*4 (A) / c base tq*8 (Out)
    const int lane = tid & 31, wp = tid >> 5;
    const float SCALE = 0.08838834764831845f;   // 1/sqrt(128)

    for (int qc = 0; qc < 64; ++qc) {
        __syncthreads();
        const float* csrc = cb + qc*64;
        for (int e = tid; e < 8192; e += 256) {
            int c = e >> 6, qq = e & 63;
            sC[e] = csrc[c*HWSZ + qq];
        }
        __syncthreads();
        // --- A = Hw^T * Cchunk ---
        float a[4][4];
#pragma unroll
        for (int i = 0; i < 4; ++i)
#pragma unroll
            for (int j = 0; j < 4; ++j) a[i][j] = 0.f;
#pragma unroll 4
        for (int c = 0; c < 128; ++c) {
            float4 hv = *(const float4*)(sH + c*64 + th*4);
            float4 cv = *(const float4*)(sC + c*64 + tq*4);
            a[0][0] = fmaf(cv.x, hv.x, a[0][0]); a[0][1] = fmaf(cv.x, hv.y, a[0][1]);
            a[0][2] = fmaf(cv.x, hv.z, a[0][2]); a[0][3] = fmaf(cv.x, hv.w, a[0][3]);
            a[1][0] = fmaf(cv.y, hv.x, a[1][0]); a[1][1] = fmaf(cv.y, hv.y, a[1][1]);
            a[1][2] = fmaf(cv.y, hv.z, a[1][2]); a[1][3] = fmaf(cv.y, hv.w, a[1][3]);
            a[2][0] = fmaf(cv.z, hv.x, a[2][0]); a[2][1] = fmaf(cv.z, hv.y, a[2][1]);
            a[2][2] = fmaf(cv.z, hv.z, a[2][2]); a[2][3] = fmaf(cv.z, hv.w, a[2][3]);
            a[3][0] = fmaf(cv.w, hv.x, a[3][0]); a[3][1] = fmaf(cv.w, hv.y, a[3][1]);
            a[3][2] = fmaf(cv.w, hv.z, a[3][2]); a[3][3] = fmaf(cv.w, hv.w, a[3][3]);
        }
#pragma unroll
        for (int qi = 0; qi < 4; ++qi) {
            float4 v;
            v.x = a[qi][0]*SCALE; v.y = a[qi][1]*SCALE;
            v.z = a[qi][2]*SCALE; v.w = a[qi][3]*SCALE;
            *(float4*)(sA + (tq*4 + qi)*64 + th*4) = v;
        }
        __syncthreads();
        // --- softmax along hh (each sA row, 64 entries) ---
#pragma unroll
        for (int k = 0; k < 8; ++k) {
            int r = wp*8 + k;
            float x0 = sA[r*64 + lane], x1 = sA[r*64 + lane + 32];
            float m = fmaxf(x0, x1);
#pragma unroll
            for (int o = 16; o > 0; o >>= 1)
                m = fmaxf(m, __shfl_xor_sync(0xffffffffu, m, o));
            float e0 = __expf(x0 - m), e1 = __expf(x1 - m);
            float ss = e0 + e1;
#pragma unroll
            for (int o = 16; o > 0; o >>= 1)
                ss += __shfl_xor_sync(0xffffffffu, ss, o);
            float inv = 1.0f / ss;
            sA[r*64 + lane]      = e0 * inv;
            sA[r*64 + lane + 32] = e1 * inv;
        }
        __syncthreads();
        // --- Out += Cchunk * P^T ---
        const int cb8 = tq * 8;
#pragma unroll 2
        for (int qq = 0; qq < 64; ++qq) {
            float4 pv = *(const float4*)(sA + qq*64 + th*4);
#pragma unroll
            for (int j = 0; j < 8; ++j) {
                float cv = sC[(cb8 + j)*64 + qq];
                oa[j][0] = fmaf(cv, pv.x, oa[j][0]);
                oa[j][1] = fmaf(cv, pv.y, oa[j][1]);
                oa[j][2] = fmaf(cv, pv.z, oa[j][2]);
                oa[j][3] = fmaf(cv, pv.w, oa[j][3]);
            }
        }
    }
    // --- epilogue: h += attn + contrast_embed[aim[b]] ---
    const float* ce = ce_tab + aim[b]*CC;
    const int cb8 = tq * 8;
#pragma unroll
    for (int j = 0; j < 8; ++j) {
        int c = cb8 + j;
        float cev = ce[c];
        float* hp = hb + c*HWSZ + w;
#pragma unroll
        for (int i = 0; i < 4; ++i) {
            int hh = th*4 + i;
            hp[hh*64] += oa[j][i] + cev;
        }
    }
}

// ---------------------------------------------------------------------------
extern "C" void kernel_launch(void* const* d_in, const int* in_sizes, int n_in,
                              void* d_out, int out_size) {
    (void)in_sizes; (void)n_in; (void)out_size;
    const float* x       = (const float*)d_in[0];
    const float* t       = (const float*)d_in[1];
    const int*   aim     = (const int*)  d_in[2];
    const float* cond    = (const float*)d_in[3];
    const float* gn1_s   = (const float*)d_in[4];
    const float* gn1_b   = (const float*)d_in[5];
    const float* conv1_w = (const float*)d_in[6];
    const float* conv1_b = (const float*)d_in[7];
    const float* mlp_w   = (const float*)d_in[8];
    const float* mlp_b   = (const float*)d_in[9];
    const float* cond_w  = (const float*)d_in[10];
    const float* cond_b  = (const float*)d_in[11];
    const float* gn2_s   = (const float*)d_in[12];
    const float* gn2_b   = (const float*)d_in[13];
    const float* conv2_w = (const float*)d_in[14];
    const float* conv2_b = (const float*)d_in[15];
    const float* ce      = (const float*)d_in[16];
    float* out = (float*)d_out;

    float *p_buf, *p_h, *p_c, *p_temb;
    cudaGetSymbolAddress((void**)&p_buf,  g_buf);
    cudaGetSymbolAddress((void**)&p_h,    g_h);
    cudaGetSymbolAddress((void**)&p_c,    g_c);
    cudaGetSymbolAddress((void**)&p_temb, g_temb);

    // temb = silu(t) @ mlp_w^T + mlp_b
    temb_kernel<<<1, 512>>>(t, mlp_w, mlp_b);
    // g_buf = silu(GN1(x))
    gn_silu_kernel<<<128, 256>>>(x, gn1_s, gn1_b, p_buf);
    // g_h = conv1(g_buf) + conv1_b + temb
    conv3x3_kernel<<<dim3(16, 4, 4), 256>>>(p_buf, conv1_w, conv1_b, p_temb,
                                            nullptr, p_h);
    // g_c = 1x1 conv of cond
    cond1x1_kernel<<<dim3(32, 4), 256>>>(cond, cond_w, cond_b);
    // attention (in-place on g_h) + contrast embed
    cudaFuncSetAttribute(attn_kernel,
                         cudaFuncAttributeMaxDynamicSharedMemorySize, 81920);
    attn_kernel<<<dim3(64, 4), 256, 81920>>>(p_h, p_c, ce, aim);
    // g_buf = silu(GN2(g_h))
    gn_silu_kernel<<<128, 256>>>(p_h, gn2_s, gn2_b, p_buf);
    // out = conv2(g_buf) + conv2_b + x
    conv3x3_kernel<<<dim3(16, 4, 4), 256>>>(p_buf, conv2_w, conv2_b, nullptr,
                                            x, out);
}